// round 3
// baseline (speedup 1.0000x reference)
#include <cuda_runtime.h>
#include <cuda_bf16.h>

// position_encoder: out[b,s,j] = x[b,s,j] + (j even ? sin : cos)(s / 10000^((j+1)/1024))
// B=4, S=8192, D=1024, fp32.
// Setup kernel (parallelized across SMs): per-column fd_j (double), sin(fd_j), cos(fd_j).
// Main kernel: seed sin/cos at chunk start via fp64 arg + sincosf, then fp32
// rotation recurrence; streaming add over 4 rows x 4 batches per block.

#define PE_S     8192
#define PE_D     1024
#define PE_B     4
#define PE_CHUNK 4
#define PE_D4    (PE_D / 4)

__device__ double g_fd[PE_D];
__device__ float  g_sf[PE_D];
__device__ float  g_cf[PE_D];

// 64 blocks x 16 threads: spreads the slow fp64 exp2/sincos across SMs.
__global__ void pe_setup_kernel() {
    const int j = blockIdx.x * blockDim.x + threadIdx.x;   // 0..1023
    const double kexp = 13.287712379549449 / 1024.0;       // log2(10000)/1024
    const double fd = exp2(-(double)(j + 1) * kexp);
    g_fd[j] = fd;
    float s, c;
    sincosf((float)fd, &s, &c);
    g_sf[j] = s;
    g_cf[j] = c;
}

__global__ __launch_bounds__(256, 6)
void position_encoder_kernel(const float4* __restrict__ x, float4* __restrict__ out) {
    const int d4 = threadIdx.x;              // columns [4*d4, 4*d4+3]
    const int s0 = blockIdx.x * PE_CHUNK;
    const int j0 = d4 * 4;

    // Seed sin/cos at s0 (fp64 argument for accuracy) + rotation coefficients.
    float sn[4], cs[4], sf[4], cf[4];
#pragma unroll
    for (int c = 0; c < 4; c++) {
        const int jc = j0 + c;
        const double fd = g_fd[jc];
        sincosf((float)((double)s0 * fd), &sn[c], &cs[c]);
        sf[c] = g_sf[jc];
        cf[c] = g_cf[jc];
    }

    const size_t sstride = (size_t)PE_D4;
    const size_t bstride = (size_t)PE_S * PE_D4;
    const float4* __restrict__ xp = x   + (size_t)s0 * sstride + d4;
    float4* __restrict__       op = out + (size_t)s0 * sstride + d4;

#pragma unroll
    for (int k = 0; k < PE_CHUNK; k++) {
        const float4 p = make_float4(sn[0], cs[1], sn[2], cs[3]);
        const size_t row = (size_t)k * sstride;
#pragma unroll
        for (int b = 0; b < PE_B; b++) {
            const size_t idx = (size_t)b * bstride + row;
            float4 v = __ldcs(&xp[idx]);          // streaming load (no reuse)
            v.x += p.x; v.y += p.y; v.z += p.z; v.w += p.w;
            __stcs(&op[idx], v);                  // streaming store (no reuse)
        }
        // angle addition: advance by fd
#pragma unroll
        for (int c = 0; c < 4; c++) {
            const float ns = fmaf(sn[c], cf[c],  cs[c] * sf[c]);
            const float nc = fmaf(cs[c], cf[c], -sn[c] * sf[c]);
            sn[c] = ns;
            cs[c] = nc;
        }
    }
}

extern "C" void kernel_launch(void* const* d_in, const int* in_sizes, int n_in,
                              void* d_out, int out_size) {
    (void)in_sizes; (void)n_in; (void)out_size;
    const float4* x = (const float4*)d_in[0];
    float4* out = (float4*)d_out;
    pe_setup_kernel<<<64, 16>>>();
    position_encoder_kernel<<<PE_S / PE_CHUNK, 256>>>(x, out);
}

// round 4
// speedup vs baseline: 1.0006x; 1.0006x over previous
#include <cuda_runtime.h>
#include <cuda_bf16.h>

// position_encoder: out[b,s,j] = x[b,s,j] + (j even ? sin : cos)(s / 10000^((j+1)/1024))
// B=4, S=8192, D=1024, fp32.
// Single kernel. Prologue: per-thread fd_j via ONE fp64 exp2 + 3 DMULs by the
// constant ratio r = 10000^(-1/1024); seed sin/cos from fp64 theta; then fp32
// rotation recurrence over a 4-row chunk x 4 batches of pure streaming adds.

#define PE_S     8192
#define PE_D     1024
#define PE_B     4
#define PE_CHUNK 4
#define PE_D4    (PE_D / 4)

__global__ __launch_bounds__(256, 5)
void position_encoder_kernel(const float4* __restrict__ x, float4* __restrict__ out) {
    const int d4 = threadIdx.x;              // columns [4*d4, 4*d4+3]
    const int s0 = blockIdx.x * PE_CHUNK;
    const int j0 = d4 * 4;

    // fd_j = 10000^(-(j+1)/1024) = 2^(-(j+1)*log2(10000)/1024)
    const double kexp = 13.287712379549449 / 1024.0;   // log2(10000)/1024
    const double r   = 0.99104585624884;               // 10000^(-1/1024)
    double fd[4];
    fd[0] = exp2(-(double)(j0 + 1) * kexp);            // one fp64 exp2 per thread
    fd[1] = fd[0] * r;
    fd[2] = fd[1] * r;
    fd[3] = fd[2] * r;

    // Seeds at s0 (fp64 argument, fp32 sincosf) + per-step rotation coefficients.
    float sn[4], cs[4], sf[4], cf[4];
#pragma unroll
    for (int c = 0; c < 4; c++) {
        sincosf((float)((double)s0 * fd[c]), &sn[c], &cs[c]);
        sincosf((float)fd[c], &sf[c], &cf[c]);
    }

    const size_t sstride = (size_t)PE_D4;
    const size_t bstride = (size_t)PE_S * PE_D4;
    const float4* __restrict__ xp = x   + (size_t)s0 * sstride + d4;
    float4* __restrict__       op = out + (size_t)s0 * sstride + d4;

#pragma unroll
    for (int k = 0; k < PE_CHUNK; k++) {
        const float4 p = make_float4(sn[0], cs[1], sn[2], cs[3]);
        const size_t row = (size_t)k * sstride;
#pragma unroll
        for (int b = 0; b < PE_B; b++) {
            const size_t idx = (size_t)b * bstride + row;
            float4 v = xp[idx];
            v.x += p.x; v.y += p.y; v.z += p.z; v.w += p.w;
            op[idx] = v;
        }
        // angle addition: advance phase by fd
#pragma unroll
        for (int c = 0; c < 4; c++) {
            const float ns = fmaf(sn[c], cf[c],  cs[c] * sf[c]);
            const float nc = fmaf(cs[c], cf[c], -sn[c] * sf[c]);
            sn[c] = ns;
            cs[c] = nc;
        }
    }
}

extern "C" void kernel_launch(void* const* d_in, const int* in_sizes, int n_in,
                              void* d_out, int out_size) {
    (void)in_sizes; (void)n_in; (void)out_size;
    const float4* x = (const float4*)d_in[0];
    float4* out = (float4*)d_out;
    position_encoder_kernel<<<PE_S / PE_CHUNK, 256>>>(x, out);
}

// round 5
// speedup vs baseline: 1.2065x; 1.2058x over previous
#include <cuda_runtime.h>
#include <cuda_bf16.h>

// position_encoder: out[b,s,j] = x[b,s,j] + (j even ? sin : cos)(s / 10000^((j+1)/1024))
// B=4, S=8192, D=1024, fp32.
// Single kernel, zero runtime fp64: per-column constants (fd_j as double,
// sin(fd_j)/cos(fd_j) as float) are baked at COMPILE TIME via constexpr
// Taylor-series exp2/sin/cos (double-accurate). Main loop: seed sincosf from
// fp64 theta, fp32 rotation recurrence, streaming float4 adds.

#define PE_S     8192
#define PE_D     1024
#define PE_B     4
#define PE_CHUNK 4
#define PE_D4    (PE_D / 4)

struct PETab {
    double fd[PE_D];   // 10000^(-(j+1)/1024)
    float  sf[PE_D];   // sin(fd_j)
    float  cf[PE_D];   // cos(fd_j)
};

// e^t for |t| < 0.7, Horner on 24-term Taylor (error ~1 ulp double)
constexpr double cexp_small(double t) {
    double r = 1.0;
    for (int k = 24; k >= 1; --k) r = 1.0 + t * r / (double)k;
    return r;
}
// sin/cos for 0 < x < 1, forward Taylor (terms decay superfast)
constexpr double csin(double x) {
    double x2 = x * x, term = x, sum = x;
    for (int k = 1; k <= 12; ++k) {
        term *= -x2 / (double)((2 * k) * (2 * k + 1));
        sum += term;
    }
    return sum;
}
constexpr double ccos(double x) {
    double x2 = x * x, term = 1.0, sum = 1.0;
    for (int k = 1; k <= 12; ++k) {
        term *= -x2 / (double)((2 * k - 1) * (2 * k));
        sum += term;
    }
    return sum;
}

constexpr PETab make_tab() {
    PETab t{};
    const double kexp = 13.287712379549449 / 1024.0;  // log2(10000)/1024
    const double ln2  = 0.6931471805599453;
    for (int j = 0; j < PE_D; ++j) {
        const double e = (double)(j + 1) * kexp;      // in (0, 13.29]
        const int    n = (int)e;                      // integer part
        const double f = e - (double)n;               // frac in [0,1)
        double v = cexp_small(-f * ln2);              // 2^-f
        for (int i = 0; i < n; ++i) v *= 0.5;         // * 2^-n (exact)
        t.fd[j] = v;
        t.sf[j] = (float)csin(v);
        t.cf[j] = (float)ccos(v);
    }
    return t;
}

__device__ constexpr PETab g_tab = make_tab();

__global__ __launch_bounds__(256, 5)
void position_encoder_kernel(const float4* __restrict__ x, float4* __restrict__ out) {
    const int d4 = threadIdx.x;              // columns [4*d4, 4*d4+3]
    const int s0 = blockIdx.x * PE_CHUNK;
    const int j0 = d4 * 4;

    // Seed sin/cos at s0 (fp64 argument -> accurate fp32 angle) + step coeffs.
    float sn[4], cs[4], sf[4], cf[4];
#pragma unroll
    for (int c = 0; c < 4; c++) {
        const int jc = j0 + c;
        const double fd = g_tab.fd[jc];
        sincosf((float)((double)s0 * fd), &sn[c], &cs[c]);
        sf[c] = g_tab.sf[jc];
        cf[c] = g_tab.cf[jc];
    }

    const size_t sstride = (size_t)PE_D4;
    const size_t bstride = (size_t)PE_S * PE_D4;
    const float4* __restrict__ xp = x   + (size_t)s0 * sstride + d4;
    float4* __restrict__       op = out + (size_t)s0 * sstride + d4;

#pragma unroll
    for (int k = 0; k < PE_CHUNK; k++) {
        const float4 p = make_float4(sn[0], cs[1], sn[2], cs[3]);
        const size_t row = (size_t)k * sstride;
#pragma unroll
        for (int b = 0; b < PE_B; b++) {
            const size_t idx = (size_t)b * bstride + row;
            float4 v = xp[idx];
            v.x += p.x; v.y += p.y; v.z += p.z; v.w += p.w;
            op[idx] = v;
        }
        // angle addition: advance phase by fd
#pragma unroll
        for (int c = 0; c < 4; c++) {
            const float ns = fmaf(sn[c], cf[c],  cs[c] * sf[c]);
            const float nc = fmaf(cs[c], cf[c], -sn[c] * sf[c]);
            sn[c] = ns;
            cs[c] = nc;
        }
    }
}

extern "C" void kernel_launch(void* const* d_in, const int* in_sizes, int n_in,
                              void* d_out, int out_size) {
    (void)in_sizes; (void)n_in; (void)out_size;
    const float4* x = (const float4*)d_in[0];
    float4* out = (float4*)d_out;
    position_encoder_kernel<<<PE_S / PE_CHUNK, 256>>>(x, out);
}

// round 6
// speedup vs baseline: 1.2163x; 1.0081x over previous
#include <cuda_runtime.h>
#include <cuda_bf16.h>

// position_encoder: out[b,s,j] = x[b,s,j] + (j even ? sin : cos)(s / 10000^((j+1)/1024))
// B=4, S=8192, D=1024, fp32.
// Single kernel, compile-time constant tables (fd_j double, sin/cos(fd_j) float).
// Per block: 2 rows x 4 batches. Both pos vectors computed up front, then ALL
// 8 float4 loads issued before any store (MLP_p1=8), 8 adds, 8 stores.

#define PE_S     8192
#define PE_D     1024
#define PE_B     4
#define PE_CHUNK 2
#define PE_D4    (PE_D / 4)

struct PETab {
    double fd[PE_D];   // 10000^(-(j+1)/1024)
    float  sf[PE_D];   // sin(fd_j)
    float  cf[PE_D];   // cos(fd_j)
};

constexpr double cexp_small(double t) {
    double r = 1.0;
    for (int k = 24; k >= 1; --k) r = 1.0 + t * r / (double)k;
    return r;
}
constexpr double csin(double x) {
    double x2 = x * x, term = x, sum = x;
    for (int k = 1; k <= 12; ++k) {
        term *= -x2 / (double)((2 * k) * (2 * k + 1));
        sum += term;
    }
    return sum;
}
constexpr double ccos(double x) {
    double x2 = x * x, term = 1.0, sum = 1.0;
    for (int k = 1; k <= 12; ++k) {
        term *= -x2 / (double)((2 * k - 1) * (2 * k));
        sum += term;
    }
    return sum;
}

constexpr PETab make_tab() {
    PETab t{};
    const double kexp = 13.287712379549449 / 1024.0;  // log2(10000)/1024
    const double ln2  = 0.6931471805599453;
    for (int j = 0; j < PE_D; ++j) {
        const double e = (double)(j + 1) * kexp;
        const int    n = (int)e;
        const double f = e - (double)n;
        double v = cexp_small(-f * ln2);              // 2^-f
        for (int i = 0; i < n; ++i) v *= 0.5;         // * 2^-n (exact)
        t.fd[j] = v;
        t.sf[j] = (float)csin(v);
        t.cf[j] = (float)ccos(v);
    }
    return t;
}

__device__ constexpr PETab g_tab = make_tab();

__global__ __launch_bounds__(256)
void position_encoder_kernel(const float4* __restrict__ x, float4* __restrict__ out) {
    const int d4 = threadIdx.x;              // columns [4*d4, 4*d4+3]
    const int s0 = blockIdx.x * PE_CHUNK;
    const int j0 = d4 * 4;

    // Seed sin/cos at s0 (fp64 argument -> accurate fp32 angle) + step coeffs.
    float sn[4], cs[4];
#pragma unroll
    for (int c = 0; c < 4; c++)
        sincosf((float)((double)s0 * g_tab.fd[j0 + c]), &sn[c], &cs[c]);

    // pos vector for row s0, then rotate once for row s0+1
    const float4 p0 = make_float4(sn[0], cs[1], sn[2], cs[3]);
    float sn1[4], cs1[4];
#pragma unroll
    for (int c = 0; c < 4; c++) {
        const float sfc = g_tab.sf[j0 + c];
        const float cfc = g_tab.cf[j0 + c];
        sn1[c] = fmaf(sn[c], cfc,  cs[c] * sfc);
        cs1[c] = fmaf(cs[c], cfc, -sn[c] * sfc);
    }
    const float4 p1 = make_float4(sn1[0], cs1[1], sn1[2], cs1[3]);

    const size_t sstride = (size_t)PE_D4;
    const size_t bstride = (size_t)PE_S * PE_D4;
    const float4* __restrict__ xp = x   + (size_t)s0 * sstride + d4;
    float4* __restrict__       op = out + (size_t)s0 * sstride + d4;

    // Front-batch ALL 8 loads (2 rows x 4 batches), then add, then store.
    float4 v[2 * PE_B];
#pragma unroll
    for (int b = 0; b < PE_B; b++) {
        v[2 * b + 0] = xp[(size_t)b * bstride];
        v[2 * b + 1] = xp[(size_t)b * bstride + sstride];
    }
#pragma unroll
    for (int b = 0; b < PE_B; b++) {
        v[2 * b + 0].x += p0.x; v[2 * b + 0].y += p0.y;
        v[2 * b + 0].z += p0.z; v[2 * b + 0].w += p0.w;
        v[2 * b + 1].x += p1.x; v[2 * b + 1].y += p1.y;
        v[2 * b + 1].z += p1.z; v[2 * b + 1].w += p1.w;
    }
#pragma unroll
    for (int b = 0; b < PE_B; b++) {
        op[(size_t)b * bstride]           = v[2 * b + 0];
        op[(size_t)b * bstride + sstride] = v[2 * b + 1];
    }
}

extern "C" void kernel_launch(void* const* d_in, const int* in_sizes, int n_in,
                              void* d_out, int out_size) {
    (void)in_sizes; (void)n_in; (void)out_size;
    const float4* x = (const float4*)d_in[0];
    float4* out = (float4*)d_out;
    position_encoder_kernel<<<PE_S / PE_CHUNK, 256>>>(x, out);
}